// round 1
// baseline (speedup 1.0000x reference)
#include <cuda_runtime.h>
#include <math.h>

#define NN 100000
#define EE 500000

// Scratch (reused sequentially: source network fully processed, then target)
__device__ float g_h [NN * 128];   // GEMM output (also aliased as N x 64)
__device__ float g_hs[NN * 128];   // conv1 output (pre-relu; relu fused into gemm64 load)
__device__ int   g_cnt[NN];
__device__ int   g_off[NN + 1];
__device__ int   g_cur[NN];
__device__ int   g_adj[EE];
__device__ float g_dis[NN];        // rsqrt(deg)
__device__ float g_inv[NN];        // 1/deg

// ---------------------------------------------------------------- degree/CSR
__global__ void zero_cnt_kernel(int n) {
    int i = blockIdx.x * blockDim.x + threadIdx.x;
    if (i < n) g_cnt[i] = 0;
}

__global__ void count_kernel(const int* __restrict__ dst, int m) {
    for (int e = blockIdx.x * blockDim.x + threadIdx.x; e < m;
         e += gridDim.x * blockDim.x)
        atomicAdd(&g_cnt[dst[e]], 1);
}

// Single-block exclusive scan over g_cnt -> g_off/g_cur, plus deg transforms.
__global__ void scan_kernel(int n) {
    __shared__ int ss[1024];
    int t = threadIdx.x;
    int chunk = (n + 1023) >> 10;
    int i0 = t * chunk;
    int i1 = min(i0 + chunk, n);
    int s = 0;
    for (int i = i0; i < i1; i++) s += g_cnt[i];
    ss[t] = s;
    __syncthreads();
    // inclusive Hillis-Steele scan
    for (int d = 1; d < 1024; d <<= 1) {
        int v = (t >= d) ? ss[t - d] : 0;
        __syncthreads();
        ss[t] += v;
        __syncthreads();
    }
    int run = ss[t] - s;  // exclusive prefix of this thread's chunk
    for (int i = i0; i < i1; i++) {
        g_off[i] = run;
        g_cur[i] = run;
        int c = g_cnt[i];
        run += c;
        float deg = (float)(c + 1);     // +1 self loop
        g_dis[i] = rsqrtf(deg);
        g_inv[i] = 1.0f / deg;
    }
    if (t == 1023) g_off[n] = ss[1023];
}

__global__ void fill_kernel(const int* __restrict__ src,
                            const int* __restrict__ dst, int m) {
    for (int e = blockIdx.x * blockDim.x + threadIdx.x; e < m;
         e += gridDim.x * blockDim.x) {
        int p = atomicAdd(&g_cur[dst[e]], 1);
        g_adj[p] = src[e];
    }
}

// ---------------------------------------------------------------- dense GEMM
// H[n, OUTC] = (RELU_IN ? relu(X) : X)[n,128] @ W[128, OUTC]
// 64 rows per block; thread computes 8 rows x 4 cols.
template <int OUTC, bool RELU_IN>
__global__ void gemm_kernel(const float* __restrict__ X,
                            const float* __restrict__ W,
                            float* __restrict__ H, int n) {
    __shared__ float sx[64 * 128];
    const int T = 2 * OUTC;  // 256 for OUTC=128, 128 for OUTC=64
    int row0 = blockIdx.x * 64;
    const float4* X4 = (const float4*)X;
    for (int i = threadIdx.x; i < 64 * 32; i += T) {
        int r = i >> 5, c4 = i & 31;
        float4 v = make_float4(0.f, 0.f, 0.f, 0.f);
        if (row0 + r < n) v = X4[(size_t)(row0 + r) * 32 + c4];
        if (RELU_IN) {
            v.x = fmaxf(v.x, 0.f); v.y = fmaxf(v.y, 0.f);
            v.z = fmaxf(v.z, 0.f); v.w = fmaxf(v.w, 0.f);
        }
        ((float4*)sx)[i] = v;
    }
    __syncthreads();

    int cg = threadIdx.x % (OUTC / 4);
    int rg = threadIdx.x / (OUTC / 4);
    int r0 = rg * 8;
    float4 acc[8];
#pragma unroll
    for (int r = 0; r < 8; r++) acc[r] = make_float4(0.f, 0.f, 0.f, 0.f);

    const float4* W4 = (const float4*)W;
#pragma unroll 4
    for (int k = 0; k < 128; k++) {
        float4 w = W4[k * (OUTC / 4) + cg];
#pragma unroll
        for (int r = 0; r < 8; r++) {
            float x = sx[(r0 + r) * 128 + k];
            acc[r].x += x * w.x;
            acc[r].y += x * w.y;
            acc[r].z += x * w.z;
            acc[r].w += x * w.w;
        }
    }
#pragma unroll
    for (int r = 0; r < 8; r++) {
        int gr = row0 + r0 + r;
        if (gr < n) ((float4*)H)[(size_t)gr * (OUTC / 4) + cg] = acc[r];
    }
}

// ---------------------------------------------------------------- aggregation
// One warp per dst row: out = sum_j h[adj[j]] * dis[adj[j]]*dis[row]
//                            + h[row]/deg[row] + bias
__global__ void agg128_kernel(const float* __restrict__ Hin,
                              const float* __restrict__ bias,
                              float* __restrict__ Out, int n) {
    int w = (blockIdx.x * blockDim.x + threadIdx.x) >> 5;
    int lane = threadIdx.x & 31;
    if (w >= n) return;
    const float4* H4 = (const float4*)Hin;
    float4 self = H4[(size_t)w * 32 + lane];
    float invd = g_inv[w];
    float disr = g_dis[w];
    float4 acc = make_float4(self.x * invd, self.y * invd,
                             self.z * invd, self.w * invd);
    int b0 = g_off[w], e0 = g_off[w + 1];
    for (int j = b0; j < e0; j++) {
        int s = g_adj[j];
        float nrm = disr * g_dis[s];
        float4 v = H4[(size_t)s * 32 + lane];
        acc.x += v.x * nrm; acc.y += v.y * nrm;
        acc.z += v.z * nrm; acc.w += v.w * nrm;
    }
    float4 bb = ((const float4*)bias)[lane];
    acc.x += bb.x; acc.y += bb.y; acc.z += bb.z; acc.w += bb.w;
    ((float4*)Out)[(size_t)w * 32 + lane] = acc;
}

__global__ void agg64_kernel(const float* __restrict__ Hin,
                             const float* __restrict__ bias,
                             float* __restrict__ Out, int n) {
    int w = (blockIdx.x * blockDim.x + threadIdx.x) >> 5;
    int lane = threadIdx.x & 31;
    if (w >= n) return;
    const float2* H2 = (const float2*)Hin;
    float2 self = H2[(size_t)w * 32 + lane];
    float invd = g_inv[w];
    float disr = g_dis[w];
    float2 acc = make_float2(self.x * invd, self.y * invd);
    int b0 = g_off[w], e0 = g_off[w + 1];
    for (int j = b0; j < e0; j++) {
        int s = g_adj[j];
        float nrm = disr * g_dis[s];
        float2 v = H2[(size_t)s * 32 + lane];
        acc.x += v.x * nrm;
        acc.y += v.y * nrm;
    }
    float2 bb = ((const float2*)bias)[lane];
    acc.x += bb.x; acc.y += bb.y;
    ((float2*)Out)[(size_t)w * 32 + lane] = acc;
}

// ---------------------------------------------------------------- decoder
// half-warp (16 lanes) per edge: dot over 64 floats, sigmoid.
__global__ void decoder_kernel(const float* __restrict__ Z,
                               const int* __restrict__ ea,
                               const int* __restrict__ eb,
                               float* __restrict__ P, int m) {
    int gid = blockIdx.x * blockDim.x + threadIdx.x;
    int e = gid >> 4;
    int l = gid & 15;
    int ec = min(e, m - 1);
    int a = ea[ec], b = eb[ec];
    const float4* Z4 = (const float4*)Z;
    float4 va = Z4[(size_t)a * 16 + l];
    float4 vb = Z4[(size_t)b * 16 + l];
    float s = va.x * vb.x + va.y * vb.y + va.z * vb.z + va.w * vb.w;
    s += __shfl_xor_sync(0xffffffffu, s, 8);
    s += __shfl_xor_sync(0xffffffffu, s, 4);
    s += __shfl_xor_sync(0xffffffffu, s, 2);
    s += __shfl_xor_sync(0xffffffffu, s, 1);
    if (l == 0 && e < m) P[e] = 1.0f / (1.0f + expf(-s));
}

// ---------------------------------------------------------------- launch
extern "C" void kernel_launch(void* const* d_in, const int* in_sizes, int n_in,
                              void* d_out, int out_size) {
    const float* xs = (const float*)d_in[0];
    const float* xt = (const float*)d_in[1];
    const int*   se = (const int*)d_in[2];
    const int*   te = (const int*)d_in[3];
    const float* W1 = (const float*)d_in[4];
    const float* b1 = (const float*)d_in[5];
    const float* W2 = (const float*)d_in[6];
    const float* b2 = (const float*)d_in[7];
    const float* W3 = (const float*)d_in[8];
    const float* b3 = (const float*)d_in[9];

    int n = in_sizes[0] / 128;   // 100000
    int m = in_sizes[2] / 2;     // 500000

    float* out = (float*)d_out;
    float* zs = out;
    float* zt = out + (size_t)n * 64;
    float* ps = zt + (size_t)n * 64;
    float* pt = ps + m;

    float *hbuf, *hsbuf;
    cudaGetSymbolAddress((void**)&hbuf, g_h);
    cudaGetSymbolAddress((void**)&hsbuf, g_hs);

    int gb_n256 = (n + 255) / 256;
    int gb_m512 = (m + 511) / 512;
    int gb_gemm = (n + 63) / 64;
    int gb_agg  = (n + 7) / 8;     // 8 warps per 256-thread block
    int gb_dec  = (m + 15) / 16;   // 16 half-warp edges per 256-thread block

    // ---- source network ----
    {
        const int* src = se;
        const int* dst = se + m;
        zero_cnt_kernel<<<gb_n256, 256>>>(n);
        count_kernel<<<gb_m512, 512>>>(dst, m);
        scan_kernel<<<1, 1024>>>(n);
        fill_kernel<<<gb_m512, 512>>>(src, dst, m);
        gemm_kernel<128, false><<<gb_gemm, 256>>>(xs, W1, hbuf, n);
        agg128_kernel<<<gb_agg, 256>>>(hbuf, b1, hsbuf, n);
        gemm_kernel<64, true><<<gb_gemm, 128>>>(hsbuf, W3, hbuf, n);
        agg64_kernel<<<gb_agg, 256>>>(hbuf, b3, zs, n);
    }
    // ---- target network ----
    {
        const int* src = te;
        const int* dst = te + m;
        zero_cnt_kernel<<<gb_n256, 256>>>(n);
        count_kernel<<<gb_m512, 512>>>(dst, m);
        scan_kernel<<<1, 1024>>>(n);
        fill_kernel<<<gb_m512, 512>>>(src, dst, m);
        gemm_kernel<128, false><<<gb_gemm, 256>>>(xt, W2, hbuf, n);
        agg128_kernel<<<gb_agg, 256>>>(hbuf, b2, hsbuf, n);
        gemm_kernel<64, true><<<gb_gemm, 128>>>(hsbuf, W3, hbuf, n);
        agg64_kernel<<<gb_agg, 256>>>(hbuf, b3, zt, n);
    }
    // ---- decoders ----
    decoder_kernel<<<gb_dec, 256>>>(zs, se, se + m, ps, m);
    decoder_kernel<<<gb_dec, 256>>>(zt, te, te + m, pt, m);
}

// round 2
// speedup vs baseline: 2.0422x; 2.0422x over previous
#include <cuda_runtime.h>
#include <math.h>

#define NN 100000
#define EE 500000
#define NB_MAX 128   // ceil(NN/1024) = 98 <= 128

// Scratch
__device__ float g_h [NN * 128];
__device__ float g_hs[NN * 128];
__device__ int   g_cnt[NN];
__device__ int   g_off[NN + 1];
__device__ int   g_cur[NN];
__device__ int   g_adj[EE];
__device__ float g_dis[NN];   // rsqrt(deg)
__device__ float g_inv[NN];   // 1/deg
__device__ int   g_bsum[NB_MAX];
__device__ int   g_bpre[NB_MAX];

// ---------------------------------------------------------------- CSR build
__global__ void zero_cnt_kernel(int n) {
    int i = blockIdx.x * blockDim.x + threadIdx.x;
    if (i < n) g_cnt[i] = 0;
}

__global__ void count_kernel(const int* __restrict__ dst, int m) {
    for (int e = blockIdx.x * blockDim.x + threadIdx.x; e < m;
         e += gridDim.x * blockDim.x)
        atomicAdd(&g_cnt[dst[e]], 1);
}

// Phase A: per-block exclusive scan (coalesced), block sums, deg transforms.
__global__ void scanA_kernel(int n) {
    __shared__ int ss[1024];
    int t = threadIdx.x;
    int i = blockIdx.x * 1024 + t;
    int c = (i < n) ? g_cnt[i] : 0;
    ss[t] = c;
    __syncthreads();
    for (int d = 1; d < 1024; d <<= 1) {
        int v = (t >= d) ? ss[t - d] : 0;
        __syncthreads();
        ss[t] += v;
        __syncthreads();
    }
    if (i < n) {
        g_off[i] = ss[t] - c;   // exclusive within block
        float deg = (float)(c + 1);
        g_dis[i] = rsqrtf(deg);
        g_inv[i] = 1.0f / deg;
    }
    if (t == 1023) g_bsum[blockIdx.x] = ss[1023];
}

// Phase B: single small block scans the block sums.
__global__ void scanB_kernel(int nb, int n) {
    __shared__ int ss[NB_MAX];
    int t = threadIdx.x;
    int c = (t < nb) ? g_bsum[t] : 0;
    ss[t] = c;
    __syncthreads();
    for (int d = 1; d < NB_MAX; d <<= 1) {
        int v = (t >= d) ? ss[t - d] : 0;
        __syncthreads();
        ss[t] += v;
        __syncthreads();
    }
    if (t < nb) g_bpre[t] = ss[t] - c;
    if (t == NB_MAX - 1) g_off[n] = ss[NB_MAX - 1];
}

// Phase C: add block prefixes.
__global__ void scanC_kernel(int n) {
    int i = blockIdx.x * 1024 + threadIdx.x;
    if (i < n) {
        int v = g_off[i] + g_bpre[i >> 10];
        g_off[i] = v;
        g_cur[i] = v;
    }
}

__global__ void fill_kernel(const int* __restrict__ src,
                            const int* __restrict__ dst, int m) {
    for (int e = blockIdx.x * blockDim.x + threadIdx.x; e < m;
         e += gridDim.x * blockDim.x) {
        int p = atomicAdd(&g_cur[dst[e]], 1);
        g_adj[p] = src[e];
    }
}

// ---------------------------------------------------------------- dense GEMM
// H[n, OUTC] = (RELU_IN ? relu(X) : X)[n,128] @ W[128, OUTC]
// 64-row x OUTC-col tile, 128 threads, 8x(OUTC/16) register blocking,
// W staged through shared in 16-row k-chunks.
template <int OUTC, bool RELU_IN>
__global__ void gemm_kernel(const float* __restrict__ X,
                            const float* __restrict__ W,
                            float* __restrict__ H, int n) {
    constexpr int KC = 16;
    constexpr int CPT = OUTC / 16;   // cols per thread: 8 or 4
    __shared__ float sx[64 * 128];
    __shared__ float sw[KC * OUTC];

    int tid = threadIdx.x;
    int row0 = blockIdx.x * 64;
    const float4* X4 = (const float4*)X;
#pragma unroll
    for (int i = tid; i < 64 * 32; i += 128) {
        int r = i >> 5, c4 = i & 31;
        float4 v = make_float4(0.f, 0.f, 0.f, 0.f);
        if (row0 + r < n) v = X4[(size_t)(row0 + r) * 32 + c4];
        if (RELU_IN) {
            v.x = fmaxf(v.x, 0.f); v.y = fmaxf(v.y, 0.f);
            v.z = fmaxf(v.z, 0.f); v.w = fmaxf(v.w, 0.f);
        }
        ((float4*)sx)[i] = v;
    }

    int tx = tid & 15;     // 16 col groups
    int ty = tid >> 4;     // 8 row groups (x8 rows)
    float acc[8][CPT];
#pragma unroll
    for (int r = 0; r < 8; r++)
#pragma unroll
        for (int c = 0; c < CPT; c++) acc[r][c] = 0.f;

    for (int kc = 0; kc < 128; kc += KC) {
        __syncthreads();   // also orders sx-load on first iter
        const float4* W4 = (const float4*)(W + kc * OUTC);
#pragma unroll
        for (int i = tid; i < KC * OUTC / 4; i += 128)
            ((float4*)sw)[i] = W4[i];
        __syncthreads();
#pragma unroll
        for (int k = 0; k < KC; k++) {
            float xv[8];
#pragma unroll
            for (int r = 0; r < 8; r++)
                xv[r] = sx[(ty * 8 + r) * 128 + kc + k];
            float wv[CPT];
#pragma unroll
            for (int c = 0; c < CPT; c++)
                wv[c] = sw[k * OUTC + tx * CPT + c];
#pragma unroll
            for (int r = 0; r < 8; r++)
#pragma unroll
                for (int c = 0; c < CPT; c++)
                    acc[r][c] += xv[r] * wv[c];
        }
    }

#pragma unroll
    for (int r = 0; r < 8; r++) {
        int gr = row0 + ty * 8 + r;
        if (gr < n) {
#pragma unroll
            for (int c = 0; c < CPT; c += 4) {
                float4 o = make_float4(acc[r][c], acc[r][c + 1],
                                       acc[r][c + 2], acc[r][c + 3]);
                *(float4*)&H[(size_t)gr * OUTC + tx * CPT + c] = o;
            }
        }
    }
}

// ---------------------------------------------------------------- aggregation
__global__ void agg128_kernel(const float* __restrict__ Hin,
                              const float* __restrict__ bias,
                              float* __restrict__ Out, int n) {
    int w = (blockIdx.x * blockDim.x + threadIdx.x) >> 5;
    int lane = threadIdx.x & 31;
    if (w >= n) return;
    const float4* H4 = (const float4*)Hin;
    float4 self = H4[(size_t)w * 32 + lane];
    float invd = g_inv[w];
    float disr = g_dis[w];
    float4 acc = make_float4(self.x * invd, self.y * invd,
                             self.z * invd, self.w * invd);
    int b0 = g_off[w], e0 = g_off[w + 1];
    for (int j = b0; j < e0; j++) {
        int s = g_adj[j];
        float nrm = disr * g_dis[s];
        float4 v = H4[(size_t)s * 32 + lane];
        acc.x += v.x * nrm; acc.y += v.y * nrm;
        acc.z += v.z * nrm; acc.w += v.w * nrm;
    }
    float4 bb = ((const float4*)bias)[lane];
    acc.x += bb.x; acc.y += bb.y; acc.z += bb.z; acc.w += bb.w;
    ((float4*)Out)[(size_t)w * 32 + lane] = acc;
}

__global__ void agg64_kernel(const float* __restrict__ Hin,
                             const float* __restrict__ bias,
                             float* __restrict__ Out, int n) {
    int w = (blockIdx.x * blockDim.x + threadIdx.x) >> 5;
    int lane = threadIdx.x & 31;
    if (w >= n) return;
    const float2* H2 = (const float2*)Hin;
    float2 self = H2[(size_t)w * 32 + lane];
    float invd = g_inv[w];
    float disr = g_dis[w];
    float2 acc = make_float2(self.x * invd, self.y * invd);
    int b0 = g_off[w], e0 = g_off[w + 1];
    for (int j = b0; j < e0; j++) {
        int s = g_adj[j];
        float nrm = disr * g_dis[s];
        float2 v = H2[(size_t)s * 32 + lane];
        acc.x += v.x * nrm;
        acc.y += v.y * nrm;
    }
    float2 bb = ((const float2*)bias)[lane];
    acc.x += bb.x; acc.y += bb.y;
    ((float2*)Out)[(size_t)w * 32 + lane] = acc;
}

// ---------------------------------------------------------------- decoder
__global__ void decoder_kernel(const float* __restrict__ Z,
                               const int* __restrict__ ea,
                               const int* __restrict__ eb,
                               float* __restrict__ P, int m) {
    int gid = blockIdx.x * blockDim.x + threadIdx.x;
    int e = gid >> 4;
    int l = gid & 15;
    int ec = min(e, m - 1);
    int a = ea[ec], b = eb[ec];
    const float4* Z4 = (const float4*)Z;
    float4 va = Z4[(size_t)a * 16 + l];
    float4 vb = Z4[(size_t)b * 16 + l];
    float s = va.x * vb.x + va.y * vb.y + va.z * vb.z + va.w * vb.w;
    s += __shfl_xor_sync(0xffffffffu, s, 8);
    s += __shfl_xor_sync(0xffffffffu, s, 4);
    s += __shfl_xor_sync(0xffffffffu, s, 2);
    s += __shfl_xor_sync(0xffffffffu, s, 1);
    if (l == 0 && e < m) P[e] = 1.0f / (1.0f + expf(-s));
}

// ---------------------------------------------------------------- launch
extern "C" void kernel_launch(void* const* d_in, const int* in_sizes, int n_in,
                              void* d_out, int out_size) {
    const float* xs = (const float*)d_in[0];
    const float* xt = (const float*)d_in[1];
    const int*   se = (const int*)d_in[2];
    const int*   te = (const int*)d_in[3];
    const float* W1 = (const float*)d_in[4];
    const float* b1 = (const float*)d_in[5];
    const float* W2 = (const float*)d_in[6];
    const float* b2 = (const float*)d_in[7];
    const float* W3 = (const float*)d_in[8];
    const float* b3 = (const float*)d_in[9];

    int n = in_sizes[0] / 128;   // 100000
    int m = in_sizes[2] / 2;     // 500000

    float* out = (float*)d_out;
    float* zs = out;
    float* zt = out + (size_t)n * 64;
    float* ps = zt + (size_t)n * 64;
    float* pt = ps + m;

    float *hbuf, *hsbuf;
    cudaGetSymbolAddress((void**)&hbuf, g_h);
    cudaGetSymbolAddress((void**)&hsbuf, g_hs);

    int nb      = (n + 1023) / 1024;       // scan blocks (98)
    int gb_n1k  = nb;
    int gb_n256 = (n + 255) / 256;
    int gb_m512 = (m + 511) / 512;
    int gb_gemm = (n + 63) / 64;
    int gb_agg  = (n + 7) / 8;
    int gb_dec  = (m + 15) / 16;

    // ---- source network ----
    // Launch order chosen so the 6th launch (ncu -s 5 -c 1) is gemm128.
    {
        const int* src = se;
        const int* dst = se + m;
        zero_cnt_kernel<<<gb_n256, 256>>>(n);                      // 0
        count_kernel<<<gb_m512, 512>>>(dst, m);                    // 1
        scanA_kernel<<<gb_n1k, 1024>>>(n);                         // 2
        scanB_kernel<<<1, NB_MAX>>>(nb, n);                        // 3
        scanC_kernel<<<gb_n1k, 1024>>>(n);                         // 4
        gemm_kernel<128, false><<<gb_gemm, 128>>>(xs, W1, hbuf, n);// 5 <- profiled
        fill_kernel<<<gb_m512, 512>>>(src, dst, m);                // 6
        agg128_kernel<<<gb_agg, 256>>>(hbuf, b1, hsbuf, n);        // 7
        gemm_kernel<64, true><<<gb_gemm, 128>>>(hsbuf, W3, hbuf, n);
        agg64_kernel<<<gb_agg, 256>>>(hbuf, b3, zs, n);
    }
    // ---- target network ----
    {
        const int* src = te;
        const int* dst = te + m;
        zero_cnt_kernel<<<gb_n256, 256>>>(n);
        count_kernel<<<gb_m512, 512>>>(dst, m);
        scanA_kernel<<<gb_n1k, 1024>>>(n);
        scanB_kernel<<<1, NB_MAX>>>(nb, n);
        scanC_kernel<<<gb_n1k, 1024>>>(n);
        fill_kernel<<<gb_m512, 512>>>(src, dst, m);
        gemm_kernel<128, false><<<gb_gemm, 128>>>(xt, W2, hbuf, n);
        agg128_kernel<<<gb_agg, 256>>>(hbuf, b2, hsbuf, n);
        gemm_kernel<64, true><<<gb_gemm, 128>>>(hsbuf, W3, hbuf, n);
        agg64_kernel<<<gb_agg, 256>>>(hbuf, b3, zt, n);
    }
    // ---- decoders ----
    decoder_kernel<<<gb_dec, 256>>>(zs, se, se + m, ps, m);
    decoder_kernel<<<gb_dec, 256>>>(zt, te, te + m, pt, m);
}

// round 3
// speedup vs baseline: 2.1968x; 1.0757x over previous
#include <cuda_runtime.h>
#include <math.h>

#define NN 100000
#define EE 500000
#define NB_MAX 128   // ceil(NN/1024) = 98 <= 128

typedef unsigned long long u64;

__device__ __forceinline__ u64 pack2(float lo, float hi) {
    u64 r;
    asm("mov.b64 %0, {%1, %2};" : "=l"(r) : "f"(lo), "f"(hi));
    return r;
}
__device__ __forceinline__ void fma2(u64& d, u64 a, u64 b) {
    asm("fma.rn.f32x2 %0, %1, %2, %0;" : "+l"(d) : "l"(a), "l"(b));
}
__device__ __forceinline__ float2 unpack2(u64 v) {
    float2 f;
    asm("mov.b64 {%0, %1}, %2;" : "=f"(f.x), "=f"(f.y) : "l"(v));
    return f;
}

// Scratch
__device__ float g_h [NN * 128];
__device__ float g_hs[NN * 128];
__device__ int   g_cnt[NN];
__device__ int   g_off[NN + 1];
__device__ int   g_cur[NN];
__device__ int   g_adj[EE];
__device__ float g_dis[NN];   // rsqrt(deg)
__device__ int   g_bsum[NB_MAX];
__device__ int   g_bpre[NB_MAX];

// ---------------------------------------------------------------- CSR build
__global__ void zero_cnt_kernel(int n) {
    int i = blockIdx.x * blockDim.x + threadIdx.x;
    if (i < n) g_cnt[i] = 0;
}

__global__ void count_kernel(const int* __restrict__ dst, int m) {
    for (int e = blockIdx.x * blockDim.x + threadIdx.x; e < m;
         e += gridDim.x * blockDim.x)
        atomicAdd(&g_cnt[dst[e]], 1);
}

// Phase A: per-block exclusive scan (coalesced), block sums, deg transforms.
__global__ void scanA_kernel(int n) {
    __shared__ int ss[1024];
    int t = threadIdx.x;
    int i = blockIdx.x * 1024 + t;
    int c = (i < n) ? g_cnt[i] : 0;
    ss[t] = c;
    __syncthreads();
    for (int d = 1; d < 1024; d <<= 1) {
        int v = (t >= d) ? ss[t - d] : 0;
        __syncthreads();
        ss[t] += v;
        __syncthreads();
    }
    if (i < n) {
        g_off[i] = ss[t] - c;   // exclusive within block
        g_dis[i] = rsqrtf((float)(c + 1));
    }
    if (t == 1023) g_bsum[blockIdx.x] = ss[1023];
}

// Phase B: single small block scans the block sums.
__global__ void scanB_kernel(int nb, int n) {
    __shared__ int ss[NB_MAX];
    int t = threadIdx.x;
    int c = (t < nb) ? g_bsum[t] : 0;
    ss[t] = c;
    __syncthreads();
    for (int d = 1; d < NB_MAX; d <<= 1) {
        int v = (t >= d) ? ss[t - d] : 0;
        __syncthreads();
        ss[t] += v;
        __syncthreads();
    }
    if (t < nb) g_bpre[t] = ss[t] - c;
    if (t == NB_MAX - 1) g_off[n] = ss[NB_MAX - 1];
}

// Phase C: add block prefixes.
__global__ void scanC_kernel(int n) {
    int i = blockIdx.x * 1024 + threadIdx.x;
    if (i < n) {
        int v = g_off[i] + g_bpre[i >> 10];
        g_off[i] = v;
        g_cur[i] = v;
    }
}

__global__ void fill_kernel(const int* __restrict__ src,
                            const int* __restrict__ dst, int m) {
    for (int e = blockIdx.x * blockDim.x + threadIdx.x; e < m;
         e += gridDim.x * blockDim.x) {
        int p = atomicAdd(&g_cur[dst[e]], 1);
        g_adj[p] = src[e];
    }
}

// ---------------------------------------------------------------- dense GEMM
// H'[r, :] = (RELU_IN ? relu(X[r]) : X[r]) @ W * dis[r]
// 64-row x OUTC-col tile, 128 threads, packed f32x2 FMA inner loop.
template <int OUTC, bool RELU_IN>
__global__ void gemm_kernel(const float* __restrict__ X,
                            const float* __restrict__ W,
                            float* __restrict__ H, int n) {
    constexpr int KC = 16;
    constexpr int CPT = OUTC / 16;   // cols per thread: 8 or 4
    constexpr int CP2 = CPT / 2;     // packed cols per thread: 4 or 2
    __shared__ float sx[64 * 128];
    __shared__ float sw[KC * OUTC];

    int tid = threadIdx.x;
    int row0 = blockIdx.x * 64;
    const float4* X4 = (const float4*)X;
#pragma unroll
    for (int i = tid; i < 64 * 32; i += 128) {
        int r = i >> 5, c4 = i & 31;
        float4 v = make_float4(0.f, 0.f, 0.f, 0.f);
        if (row0 + r < n) v = X4[(size_t)(row0 + r) * 32 + c4];
        if (RELU_IN) {
            v.x = fmaxf(v.x, 0.f); v.y = fmaxf(v.y, 0.f);
            v.z = fmaxf(v.z, 0.f); v.w = fmaxf(v.w, 0.f);
        }
        ((float4*)sx)[i] = v;
    }

    int tx = tid & 15;     // 16 col groups
    int ty = tid >> 4;     // 8 row groups (x8 rows)
    u64 acc2[8][CP2];
    u64 zz = pack2(0.f, 0.f);
#pragma unroll
    for (int r = 0; r < 8; r++)
#pragma unroll
        for (int c = 0; c < CP2; c++) acc2[r][c] = zz;

    for (int kc = 0; kc < 128; kc += KC) {
        __syncthreads();
        const float4* W4 = (const float4*)(W + kc * OUTC);
#pragma unroll
        for (int i = tid; i < KC * OUTC / 4; i += 128)
            ((float4*)sw)[i] = W4[i];
        __syncthreads();
#pragma unroll
        for (int k = 0; k < KC; k++) {
            u64 xp[8];
#pragma unroll
            for (int r = 0; r < 8; r++) {
                float xv = sx[(ty * 8 + r) * 128 + kc + k];
                xp[r] = pack2(xv, xv);
            }
            u64 wv2[CP2];
            const u64* sw2 = (const u64*)(sw + k * OUTC + tx * CPT);
#pragma unroll
            for (int c = 0; c < CP2; c++) wv2[c] = sw2[c];
#pragma unroll
            for (int r = 0; r < 8; r++)
#pragma unroll
                for (int c = 0; c < CP2; c++)
                    fma2(acc2[r][c], xp[r], wv2[c]);
        }
    }

#pragma unroll
    for (int r = 0; r < 8; r++) {
        int gr = row0 + ty * 8 + r;
        if (gr < n) {
            float ds = g_dis[gr];
#pragma unroll
            for (int c = 0; c < CP2; c += 2) {
                float2 a = unpack2(acc2[r][c]);
                float2 b = unpack2(acc2[r][c + 1]);
                float4 o = make_float4(a.x * ds, a.y * ds, b.x * ds, b.y * ds);
                *(float4*)&H[(size_t)gr * OUTC + tx * CPT + c * 2] = o;
            }
        }
    }
}

// ---------------------------------------------------------------- aggregation
// out[w] = dis[w] * (h'[w] + sum_j h'[adj[j]]) + bias     (h' pre-scaled by dis)
__global__ void agg128_kernel(const float* __restrict__ Hin,
                              const float* __restrict__ bias,
                              float* __restrict__ Out, int n) {
    int w = (blockIdx.x * blockDim.x + threadIdx.x) >> 5;
    int lane = threadIdx.x & 31;
    if (w >= n) return;
    const float4* H4 = (const float4*)Hin;
    float4 acc = H4[(size_t)w * 32 + lane];
    int b0 = g_off[w], e0 = g_off[w + 1];
    for (int j = b0; j < e0; j++) {
        int s = g_adj[j];
        float4 v = H4[(size_t)s * 32 + lane];
        acc.x += v.x; acc.y += v.y; acc.z += v.z; acc.w += v.w;
    }
    float ds = g_dis[w];
    float4 bb = ((const float4*)bias)[lane];
    acc.x = acc.x * ds + bb.x;
    acc.y = acc.y * ds + bb.y;
    acc.z = acc.z * ds + bb.z;
    acc.w = acc.w * ds + bb.w;
    ((float4*)Out)[(size_t)w * 32 + lane] = acc;
}

__global__ void agg64_kernel(const float* __restrict__ Hin,
                             const float* __restrict__ bias,
                             float* __restrict__ Out, int n) {
    int w = (blockIdx.x * blockDim.x + threadIdx.x) >> 5;
    int lane = threadIdx.x & 31;
    if (w >= n) return;
    const float2* H2 = (const float2*)Hin;
    float2 acc = H2[(size_t)w * 32 + lane];
    int b0 = g_off[w], e0 = g_off[w + 1];
    for (int j = b0; j < e0; j++) {
        int s = g_adj[j];
        float2 v = H2[(size_t)s * 32 + lane];
        acc.x += v.x;
        acc.y += v.y;
    }
    float ds = g_dis[w];
    float2 bb = ((const float2*)bias)[lane];
    acc.x = acc.x * ds + bb.x;
    acc.y = acc.y * ds + bb.y;
    ((float2*)Out)[(size_t)w * 32 + lane] = acc;
}

// ---------------------------------------------------------------- decoder
__global__ void decoder_kernel(const float* __restrict__ Z,
                               const int* __restrict__ ea,
                               const int* __restrict__ eb,
                               float* __restrict__ P, int m) {
    int gid = blockIdx.x * blockDim.x + threadIdx.x;
    int e = gid >> 4;
    int l = gid & 15;
    int ec = min(e, m - 1);
    int a = ea[ec], b = eb[ec];
    const float4* Z4 = (const float4*)Z;
    float4 va = Z4[(size_t)a * 16 + l];
    float4 vb = Z4[(size_t)b * 16 + l];
    float s = va.x * vb.x + va.y * vb.y + va.z * vb.z + va.w * vb.w;
    s += __shfl_xor_sync(0xffffffffu, s, 8);
    s += __shfl_xor_sync(0xffffffffu, s, 4);
    s += __shfl_xor_sync(0xffffffffu, s, 2);
    s += __shfl_xor_sync(0xffffffffu, s, 1);
    if (l == 0 && e < m) P[e] = 1.0f / (1.0f + expf(-s));
}

// ---------------------------------------------------------------- launch
extern "C" void kernel_launch(void* const* d_in, const int* in_sizes, int n_in,
                              void* d_out, int out_size) {
    const float* xs = (const float*)d_in[0];
    const float* xt = (const float*)d_in[1];
    const int*   se = (const int*)d_in[2];
    const int*   te = (const int*)d_in[3];
    const float* W1 = (const float*)d_in[4];
    const float* b1 = (const float*)d_in[5];
    const float* W2 = (const float*)d_in[6];
    const float* b2 = (const float*)d_in[7];
    const float* W3 = (const float*)d_in[8];
    const float* b3 = (const float*)d_in[9];

    int n = in_sizes[0] / 128;   // 100000
    int m = in_sizes[2] / 2;     // 500000

    float* out = (float*)d_out;
    float* zs = out;
    float* zt = out + (size_t)n * 64;
    float* ps = zt + (size_t)n * 64;
    float* pt = ps + m;

    float *hbuf, *hsbuf;
    cudaGetSymbolAddress((void**)&hbuf, g_h);
    cudaGetSymbolAddress((void**)&hsbuf, g_hs);

    int nb      = (n + 1023) / 1024;       // 98
    int gb_n256 = (n + 255) / 256;
    int gb_m512 = (m + 511) / 512;
    int gb_gemm = (n + 63) / 64;
    int gb_agg  = (n + 7) / 8;
    int gb_dec  = (m + 15) / 16;

    // ---- source network ----
    // gemm128 placed at launch slot 3 (observed ncu capture slot).
    {
        const int* src = se;
        const int* dst = se + m;
        zero_cnt_kernel<<<gb_n256, 256>>>(n);                       // 0
        count_kernel<<<gb_m512, 512>>>(dst, m);                     // 1
        scanA_kernel<<<nb, 1024>>>(n);                              // 2 (dis ready)
        gemm_kernel<128, false><<<gb_gemm, 128>>>(xs, W1, hbuf, n); // 3 <- profiled
        scanB_kernel<<<1, NB_MAX>>>(nb, n);                         // 4
        scanC_kernel<<<nb, 1024>>>(n);                              // 5
        fill_kernel<<<gb_m512, 512>>>(src, dst, m);                 // 6
        agg128_kernel<<<gb_agg, 256>>>(hbuf, b1, hsbuf, n);         // 7
        gemm_kernel<64, true><<<gb_gemm, 128>>>(hsbuf, W3, hbuf, n);
        agg64_kernel<<<gb_agg, 256>>>(hbuf, b3, zs, n);
    }
    // ---- target network ----
    {
        const int* src = te;
        const int* dst = te + m;
        zero_cnt_kernel<<<gb_n256, 256>>>(n);
        count_kernel<<<gb_m512, 512>>>(dst, m);
        scanA_kernel<<<nb, 1024>>>(n);
        scanB_kernel<<<1, NB_MAX>>>(nb, n);
        scanC_kernel<<<nb, 1024>>>(n);
        fill_kernel<<<gb_m512, 512>>>(src, dst, m);
        gemm_kernel<128, false><<<gb_gemm, 128>>>(xt, W2, hbuf, n);
        agg128_kernel<<<gb_agg, 256>>>(hbuf, b2, hsbuf, n);
        gemm_kernel<64, true><<<gb_gemm, 128>>>(hsbuf, W3, hbuf, n);
        agg64_kernel<<<gb_agg, 256>>>(hbuf, b3, zt, n);
    }
    // ---- decoders ----
    decoder_kernel<<<gb_dec, 256>>>(zs, se, se + m, ps, m);
    decoder_kernel<<<gb_dec, 256>>>(zt, te, te + m, pt, m);
}

// round 4
// speedup vs baseline: 2.3517x; 1.0705x over previous
#include <cuda_runtime.h>
#include <math.h>

#define NN 100000
#define EE 500000
#define NB_MAX 128   // ceil(NN/1024) = 98 <= 128

typedef unsigned long long u64;

__device__ __forceinline__ u64 pack2(float lo, float hi) {
    u64 r;
    asm("mov.b64 %0, {%1, %2};" : "=l"(r) : "f"(lo), "f"(hi));
    return r;
}
__device__ __forceinline__ void fma2(u64& d, u64 a, u64 b) {
    asm("fma.rn.f32x2 %0, %1, %2, %0;" : "+l"(d) : "l"(a), "l"(b));
}
__device__ __forceinline__ float2 unpack2(u64 v) {
    float2 f;
    asm("mov.b64 {%0, %1}, %2;" : "=f"(f.x), "=f"(f.y) : "l"(v));
    return f;
}

// Scratch
__device__ float g_h [NN * 128];
__device__ float g_hs[NN * 128];
__device__ int   g_cnt[NN];
__device__ int   g_off[NN + 1];
__device__ int   g_cur[NN];
__device__ int   g_adj[EE];
__device__ float g_dis[NN];   // rsqrt(deg)
__device__ int   g_bsum[NB_MAX];
__device__ int   g_bpre[NB_MAX];

// ---------------------------------------------------------------- CSR build
__global__ void zero_cnt_kernel(int n) {
    int i = blockIdx.x * blockDim.x + threadIdx.x;
    if (i < n) g_cnt[i] = 0;
}

__global__ void count_kernel(const int* __restrict__ dst, int m) {
    for (int e = blockIdx.x * blockDim.x + threadIdx.x; e < m;
         e += gridDim.x * blockDim.x)
        atomicAdd(&g_cnt[dst[e]], 1);
}

__global__ void scanA_kernel(int n) {
    __shared__ int ss[1024];
    int t = threadIdx.x;
    int i = blockIdx.x * 1024 + t;
    int c = (i < n) ? g_cnt[i] : 0;
    ss[t] = c;
    __syncthreads();
    for (int d = 1; d < 1024; d <<= 1) {
        int v = (t >= d) ? ss[t - d] : 0;
        __syncthreads();
        ss[t] += v;
        __syncthreads();
    }
    if (i < n) {
        g_off[i] = ss[t] - c;
        g_dis[i] = rsqrtf((float)(c + 1));
    }
    if (t == 1023) g_bsum[blockIdx.x] = ss[1023];
}

__global__ void scanB_kernel(int nb, int n) {
    __shared__ int ss[NB_MAX];
    int t = threadIdx.x;
    int c = (t < nb) ? g_bsum[t] : 0;
    ss[t] = c;
    __syncthreads();
    for (int d = 1; d < NB_MAX; d <<= 1) {
        int v = (t >= d) ? ss[t - d] : 0;
        __syncthreads();
        ss[t] += v;
        __syncthreads();
    }
    if (t < nb) g_bpre[t] = ss[t] - c;
    if (t == NB_MAX - 1) g_off[n] = ss[NB_MAX - 1];
}

__global__ void scanC_kernel(int n) {
    int i = blockIdx.x * 1024 + threadIdx.x;
    if (i < n) {
        int v = g_off[i] + g_bpre[i >> 10];
        g_off[i] = v;
        g_cur[i] = v;
    }
}

__global__ void fill_kernel(const int* __restrict__ src,
                            const int* __restrict__ dst, int m) {
    for (int e = blockIdx.x * blockDim.x + threadIdx.x; e < m;
         e += gridDim.x * blockDim.x) {
        int p = atomicAdd(&g_cur[dst[e]], 1);
        g_adj[p] = src[e];
    }
}

// ---------------------------------------------------------------- dense GEMM
// H'[r, :] = (RELU_IN ? relu(X[r]) : X[r]) @ W * dis[r]
// 64-row x OUTC-col tile, 128 threads; f32x2 packed FMAs; x batched via
// LDS128 over 4-k groups; w loaded as LDS128 pairs.
template <int OUTC, bool RELU_IN>
__global__ void __launch_bounds__(128, 4)
gemm_kernel(const float* __restrict__ X,
            const float* __restrict__ W,
            float* __restrict__ H, int n) {
    constexpr int KC = 16;
    constexpr int CPT = OUTC / 16;   // cols per thread: 8 or 4
    constexpr int CP2 = CPT / 2;     // packed cols per thread: 4 or 2
    __shared__ float sx[64 * 128];
    __shared__ float sw[KC * OUTC];

    int tid = threadIdx.x;
    int row0 = blockIdx.x * 64;
    const float4* X4 = (const float4*)X;
#pragma unroll
    for (int i = tid; i < 64 * 32; i += 128) {
        int r = i >> 5, c4 = i & 31;
        float4 v = make_float4(0.f, 0.f, 0.f, 0.f);
        if (row0 + r < n) v = X4[(size_t)(row0 + r) * 32 + c4];
        if (RELU_IN) {
            v.x = fmaxf(v.x, 0.f); v.y = fmaxf(v.y, 0.f);
            v.z = fmaxf(v.z, 0.f); v.w = fmaxf(v.w, 0.f);
        }
        ((float4*)sx)[i] = v;
    }

    int tx = tid & 15;     // 16 col groups
    int ty = tid >> 4;     // 8 row groups (x8 rows)
    u64 acc2[8][CP2];
    u64 zz = pack2(0.f, 0.f);
#pragma unroll
    for (int r = 0; r < 8; r++)
#pragma unroll
        for (int c = 0; c < CP2; c++) acc2[r][c] = zz;

    for (int kc = 0; kc < 128; kc += KC) {
        __syncthreads();
        const float4* W4 = (const float4*)(W + kc * OUTC);
#pragma unroll
        for (int i = tid; i < KC * OUTC / 4; i += 128)
            ((float4*)sw)[i] = W4[i];
        __syncthreads();
#pragma unroll
        for (int k4 = 0; k4 < KC / 4; k4++) {
            // batch x loads: one LDS128 per row covers 4 k values
            float4 xq[8];
#pragma unroll
            for (int r = 0; r < 8; r++)
                xq[r] = *(const float4*)&sx[(ty * 8 + r) * 128 + kc + k4 * 4];
#pragma unroll
            for (int kk = 0; kk < 4; kk++) {
                u64 wv2[CP2];
                const u64* sw2 =
                    (const u64*)(sw + (k4 * 4 + kk) * OUTC + tx * CPT);
#pragma unroll
                for (int c = 0; c < CP2; c++) wv2[c] = sw2[c];
#pragma unroll
                for (int r = 0; r < 8; r++) {
                    float xv = ((const float*)&xq[r])[kk];
                    u64 xp = pack2(xv, xv);
#pragma unroll
                    for (int c = 0; c < CP2; c++)
                        fma2(acc2[r][c], xp, wv2[c]);
                }
            }
        }
    }

#pragma unroll
    for (int r = 0; r < 8; r++) {
        int gr = row0 + ty * 8 + r;
        if (gr < n) {
            float ds = g_dis[gr];
#pragma unroll
            for (int c = 0; c < CP2; c += 2) {
                float2 a = unpack2(acc2[r][c]);
                float2 b = unpack2(acc2[r][c + 1]);
                float4 o = make_float4(a.x * ds, a.y * ds, b.x * ds, b.y * ds);
                *(float4*)&H[(size_t)gr * OUTC + tx * CPT + c * 2] = o;
            }
        }
    }
}

// ---------------------------------------------------------------- aggregation
// out[w] = dis[w] * (h'[w] + sum_j h'[adj[j]]) + bias     (h' pre-scaled by dis)
__global__ void agg128_kernel(const float* __restrict__ Hin,
                              const float* __restrict__ bias,
                              float* __restrict__ Out, int n) {
    int w = (blockIdx.x * blockDim.x + threadIdx.x) >> 5;
    int lane = threadIdx.x & 31;
    if (w >= n) return;
    const float4* H4 = (const float4*)Hin;
    float4 acc = H4[(size_t)w * 32 + lane];
    int b0 = g_off[w], e0 = g_off[w + 1];
    for (int j = b0; j < e0; j++) {
        int s = g_adj[j];
        float4 v = H4[(size_t)s * 32 + lane];
        acc.x += v.x; acc.y += v.y; acc.z += v.z; acc.w += v.w;
    }
    float ds = g_dis[w];
    float4 bb = ((const float4*)bias)[lane];
    acc.x = acc.x * ds + bb.x;
    acc.y = acc.y * ds + bb.y;
    acc.z = acc.z * ds + bb.z;
    acc.w = acc.w * ds + bb.w;
    ((float4*)Out)[(size_t)w * 32 + lane] = acc;
}

__global__ void agg64_kernel(const float* __restrict__ Hin,
                             const float* __restrict__ bias,
                             float* __restrict__ Out, int n) {
    int w = (blockIdx.x * blockDim.x + threadIdx.x) >> 5;
    int lane = threadIdx.x & 31;
    if (w >= n) return;
    const float2* H2 = (const float2*)Hin;
    float2 acc = H2[(size_t)w * 32 + lane];
    int b0 = g_off[w], e0 = g_off[w + 1];
    for (int j = b0; j < e0; j++) {
        int s = g_adj[j];
        float2 v = H2[(size_t)s * 32 + lane];
        acc.x += v.x;
        acc.y += v.y;
    }
    float ds = g_dis[w];
    float2 bb = ((const float2*)bias)[lane];
    acc.x = acc.x * ds + bb.x;
    acc.y = acc.y * ds + bb.y;
    ((float2*)Out)[(size_t)w * 32 + lane] = acc;
}

// ---------------------------------------------------------------- decoder
__global__ void decoder_kernel(const float* __restrict__ Z,
                               const int* __restrict__ ea,
                               const int* __restrict__ eb,
                               float* __restrict__ P, int m) {
    int gid = blockIdx.x * blockDim.x + threadIdx.x;
    int e = gid >> 4;
    int l = gid & 15;
    int ec = min(e, m - 1);
    int a = ea[ec], b = eb[ec];
    const float4* Z4 = (const float4*)Z;
    float4 va = Z4[(size_t)a * 16 + l];
    float4 vb = Z4[(size_t)b * 16 + l];
    float s = va.x * vb.x + va.y * vb.y + va.z * vb.z + va.w * vb.w;
    s += __shfl_xor_sync(0xffffffffu, s, 8);
    s += __shfl_xor_sync(0xffffffffu, s, 4);
    s += __shfl_xor_sync(0xffffffffu, s, 2);
    s += __shfl_xor_sync(0xffffffffu, s, 1);
    if (l == 0 && e < m) P[e] = 1.0f / (1.0f + expf(-s));
}

// ---------------------------------------------------------------- launch
extern "C" void kernel_launch(void* const* d_in, const int* in_sizes, int n_in,
                              void* d_out, int out_size) {
    const float* xs = (const float*)d_in[0];
    const float* xt = (const float*)d_in[1];
    const int*   se = (const int*)d_in[2];
    const int*   te = (const int*)d_in[3];
    const float* W1 = (const float*)d_in[4];
    const float* b1 = (const float*)d_in[5];
    const float* W2 = (const float*)d_in[6];
    const float* b2 = (const float*)d_in[7];
    const float* W3 = (const float*)d_in[8];
    const float* b3 = (const float*)d_in[9];

    int n = in_sizes[0] / 128;   // 100000
    int m = in_sizes[2] / 2;     // 500000

    float* out = (float*)d_out;
    float* zs = out;
    float* zt = out + (size_t)n * 64;
    float* ps = zt + (size_t)n * 64;
    float* pt = ps + m;

    float *hbuf, *hsbuf;
    cudaGetSymbolAddress((void**)&hbuf, g_h);
    cudaGetSymbolAddress((void**)&hsbuf, g_hs);

    int nb      = (n + 1023) / 1024;       // 98
    int gb_n256 = (n + 255) / 256;
    int gb_m512 = (m + 511) / 512;
    int gb_gemm = (n + 63) / 64;
    int gb_agg  = (n + 7) / 8;
    int gb_dec  = (m + 15) / 16;

    // ---- source network ----
    // gemm128 at launch slot 3 (observed ncu capture slot).
    {
        const int* src = se;
        const int* dst = se + m;
        zero_cnt_kernel<<<gb_n256, 256>>>(n);                       // 0
        count_kernel<<<gb_m512, 512>>>(dst, m);                     // 1
        scanA_kernel<<<nb, 1024>>>(n);                              // 2 (dis ready)
        gemm_kernel<128, false><<<gb_gemm, 128>>>(xs, W1, hbuf, n); // 3 <- profiled
        scanB_kernel<<<1, NB_MAX>>>(nb, n);                         // 4
        scanC_kernel<<<nb, 1024>>>(n);                              // 5
        fill_kernel<<<gb_m512, 512>>>(src, dst, m);                 // 6
        agg128_kernel<<<gb_agg, 256>>>(hbuf, b1, hsbuf, n);         // 7
        gemm_kernel<64, true><<<gb_gemm, 128>>>(hsbuf, W3, hbuf, n);
        agg64_kernel<<<gb_agg, 256>>>(hbuf, b3, zs, n);
    }
    // ---- target network ----
    {
        const int* src = te;
        const int* dst = te + m;
        zero_cnt_kernel<<<gb_n256, 256>>>(n);
        count_kernel<<<gb_m512, 512>>>(dst, m);
        scanA_kernel<<<nb, 1024>>>(n);
        scanB_kernel<<<1, NB_MAX>>>(nb, n);
        scanC_kernel<<<nb, 1024>>>(n);
        fill_kernel<<<gb_m512, 512>>>(src, dst, m);
        gemm_kernel<128, false><<<gb_gemm, 128>>>(xt, W2, hbuf, n);
        agg128_kernel<<<gb_agg, 256>>>(hbuf, b2, hsbuf, n);
        gemm_kernel<64, true><<<gb_gemm, 128>>>(hsbuf, W3, hbuf, n);
        agg64_kernel<<<gb_agg, 256>>>(hbuf, b3, zt, n);
    }
    // ---- decoders ----
    decoder_kernel<<<gb_dec, 256>>>(zs, se, se + m, ps, m);
    decoder_kernel<<<gb_dec, 256>>>(zt, te, te + m, pt, m);
}

// round 5
// speedup vs baseline: 2.4568x; 1.0447x over previous
#include <cuda_runtime.h>
#include <math.h>

#define NN 100000
#define EE 500000
#define NB_MAX 128   // ceil(NN/1024) = 98 <= 128

typedef unsigned long long u64;

__device__ __forceinline__ u64 pack2(float lo, float hi) {
    u64 r;
    asm("mov.b64 %0, {%1, %2};" : "=l"(r) : "f"(lo), "f"(hi));
    return r;
}
__device__ __forceinline__ void fma2(u64& d, u64 a, u64 b) {
    asm("fma.rn.f32x2 %0, %1, %2, %0;" : "+l"(d) : "l"(a), "l"(b));
}
__device__ __forceinline__ float2 unpack2(u64 v) {
    float2 f;
    asm("mov.b64 {%0, %1}, %2;" : "=f"(f.x), "=f"(f.y) : "l"(v));
    return f;
}

// Scratch
__device__ float g_h [NN * 128];
__device__ float g_hs[NN * 128];
__device__ int   g_cnt[NN];
__device__ int   g_off[NN + 1];
__device__ int   g_cur[NN];
__device__ int   g_adj[EE];
__device__ float g_dis[NN];   // rsqrt(deg)
__device__ int   g_bsum[NB_MAX];
__device__ int   g_bpre[NB_MAX];

// ---------------------------------------------------------------- CSR build
__global__ void zero_cnt_kernel(int n) {
    int i = blockIdx.x * blockDim.x + threadIdx.x;
    if (i < n) g_cnt[i] = 0;
}

__global__ void count_kernel(const int* __restrict__ dst, int m) {
    for (int e = blockIdx.x * blockDim.x + threadIdx.x; e < m;
         e += gridDim.x * blockDim.x)
        atomicAdd(&g_cnt[dst[e]], 1);
}

__global__ void scanA_kernel(int n) {
    __shared__ int ss[1024];
    int t = threadIdx.x;
    int i = blockIdx.x * 1024 + t;
    int c = (i < n) ? g_cnt[i] : 0;
    ss[t] = c;
    __syncthreads();
    for (int d = 1; d < 1024; d <<= 1) {
        int v = (t >= d) ? ss[t - d] : 0;
        __syncthreads();
        ss[t] += v;
        __syncthreads();
    }
    if (i < n) {
        g_off[i] = ss[t] - c;
        g_dis[i] = rsqrtf((float)(c + 1));
    }
    if (t == 1023) g_bsum[blockIdx.x] = ss[1023];
}

__global__ void scanB_kernel(int nb, int n) {
    __shared__ int ss[NB_MAX];
    int t = threadIdx.x;
    int c = (t < nb) ? g_bsum[t] : 0;
    ss[t] = c;
    __syncthreads();
    for (int d = 1; d < NB_MAX; d <<= 1) {
        int v = (t >= d) ? ss[t - d] : 0;
        __syncthreads();
        ss[t] += v;
        __syncthreads();
    }
    if (t < nb) g_bpre[t] = ss[t] - c;
    if (t == NB_MAX - 1) g_off[n] = ss[NB_MAX - 1];
}

__global__ void scanC_kernel(int n) {
    int i = blockIdx.x * 1024 + threadIdx.x;
    if (i < n) {
        int v = g_off[i] + g_bpre[i >> 10];
        g_off[i] = v;
        g_cur[i] = v;
    }
}

__global__ void fill_kernel(const int* __restrict__ src,
                            const int* __restrict__ dst, int m) {
    for (int e = blockIdx.x * blockDim.x + threadIdx.x; e < m;
         e += gridDim.x * blockDim.x) {
        int p = atomicAdd(&g_cur[dst[e]], 1);
        g_adj[p] = src[e];
    }
}

// ---------------------------------------------------------------- dense GEMM
// H'[r, :] = (RELU_IN ? relu(X[r]) : X[r]) @ W * dis[r]
// 64-row x OUTC-col tile, 128 threads; f32x2 packed FMAs.
// Thread owns col PAIRS strided by 32: cols tx*2 + 32*c  -> conflict-free
// LDS64 W loads (16 lanes cover one contiguous 128B line).
template <int OUTC, bool RELU_IN>
__global__ void __launch_bounds__(128, 4)
gemm_kernel(const float* __restrict__ X,
            const float* __restrict__ W,
            float* __restrict__ H, int n) {
    constexpr int KC = 16;
    constexpr int CP2 = OUTC / 32;   // packed col-pairs per thread: 4 or 2
    __shared__ float sx[64 * 128];
    __shared__ float sw[KC * OUTC];

    int tid = threadIdx.x;
    int row0 = blockIdx.x * 64;
    const float4* X4 = (const float4*)X;
#pragma unroll
    for (int i = tid; i < 64 * 32; i += 128) {
        int r = i >> 5, c4 = i & 31;
        float4 v = make_float4(0.f, 0.f, 0.f, 0.f);
        if (row0 + r < n) v = X4[(size_t)(row0 + r) * 32 + c4];
        if (RELU_IN) {
            v.x = fmaxf(v.x, 0.f); v.y = fmaxf(v.y, 0.f);
            v.z = fmaxf(v.z, 0.f); v.w = fmaxf(v.w, 0.f);
        }
        ((float4*)sx)[i] = v;
    }

    int tx = tid & 15;     // 16 col groups (pair tx*2 + 32*c)
    int ty = tid >> 4;     // 8 row groups (x8 rows)
    u64 acc2[8][CP2];
    u64 zz = pack2(0.f, 0.f);
#pragma unroll
    for (int r = 0; r < 8; r++)
#pragma unroll
        for (int c = 0; c < CP2; c++) acc2[r][c] = zz;

    for (int kc = 0; kc < 128; kc += KC) {
        __syncthreads();
        const float4* W4 = (const float4*)(W + kc * OUTC);
#pragma unroll
        for (int i = tid; i < KC * OUTC / 4; i += 128)
            ((float4*)sw)[i] = W4[i];
        __syncthreads();
#pragma unroll
        for (int k4 = 0; k4 < KC / 4; k4++) {
            float4 xq[8];
#pragma unroll
            for (int r = 0; r < 8; r++)
                xq[r] = *(const float4*)&sx[(ty * 8 + r) * 128 + kc + k4 * 4];
#pragma unroll
            for (int kk = 0; kk < 4; kk++) {
                u64 wv2[CP2];
                const float* swk = sw + (k4 * 4 + kk) * OUTC + tx * 2;
#pragma unroll
                for (int c = 0; c < CP2; c++)
                    wv2[c] = *(const u64*)(swk + 32 * c);
#pragma unroll
                for (int r = 0; r < 8; r++) {
                    float xv = ((const float*)&xq[r])[kk];
                    u64 xp = pack2(xv, xv);
#pragma unroll
                    for (int c = 0; c < CP2; c++)
                        fma2(acc2[r][c], xp, wv2[c]);
                }
            }
        }
    }

#pragma unroll
    for (int r = 0; r < 8; r++) {
        int gr = row0 + ty * 8 + r;
        if (gr < n) {
            float ds = g_dis[gr];
            float* hrow = H + (size_t)gr * OUTC + tx * 2;
#pragma unroll
            for (int c = 0; c < CP2; c++) {
                float2 a = unpack2(acc2[r][c]);
                a.x *= ds; a.y *= ds;
                *(float2*)(hrow + 32 * c) = a;
            }
        }
    }
}

// ---------------------------------------------------------------- aggregation
// out[w] = dis[w] * (h'[w] + sum_j h'[adj[j]]) + bias     (h' pre-scaled by dis)
__global__ void agg128_kernel(const float* __restrict__ Hin,
                              const float* __restrict__ bias,
                              float* __restrict__ Out, int n) {
    int w = (blockIdx.x * blockDim.x + threadIdx.x) >> 5;
    int lane = threadIdx.x & 31;
    if (w >= n) return;
    const float4* H4 = (const float4*)Hin;
    float4 acc = H4[(size_t)w * 32 + lane];
    int b0 = g_off[w], e0 = g_off[w + 1];
    for (int j = b0; j < e0; j++) {
        int s = g_adj[j];
        float4 v = H4[(size_t)s * 32 + lane];
        acc.x += v.x; acc.y += v.y; acc.z += v.z; acc.w += v.w;
    }
    float ds = g_dis[w];
    float4 bb = ((const float4*)bias)[lane];
    acc.x = acc.x * ds + bb.x;
    acc.y = acc.y * ds + bb.y;
    acc.z = acc.z * ds + bb.z;
    acc.w = acc.w * ds + bb.w;
    ((float4*)Out)[(size_t)w * 32 + lane] = acc;
}

__global__ void agg64_kernel(const float* __restrict__ Hin,
                             const float* __restrict__ bias,
                             float* __restrict__ Out, int n) {
    int w = (blockIdx.x * blockDim.x + threadIdx.x) >> 5;
    int lane = threadIdx.x & 31;
    if (w >= n) return;
    const float2* H2 = (const float2*)Hin;
    float2 acc = H2[(size_t)w * 32 + lane];
    int b0 = g_off[w], e0 = g_off[w + 1];
    for (int j = b0; j < e0; j++) {
        int s = g_adj[j];
        float2 v = H2[(size_t)s * 32 + lane];
        acc.x += v.x;
        acc.y += v.y;
    }
    float ds = g_dis[w];
    float2 bb = ((const float2*)bias)[lane];
    acc.x = acc.x * ds + bb.x;
    acc.y = acc.y * ds + bb.y;
    ((float2*)Out)[(size_t)w * 32 + lane] = acc;
}

// ---------------------------------------------------------------- decoder
__global__ void decoder_kernel(const float* __restrict__ Z,
                               const int* __restrict__ ea,
                               const int* __restrict__ eb,
                               float* __restrict__ P, int m) {
    int gid = blockIdx.x * blockDim.x + threadIdx.x;
    int e = gid >> 4;
    int l = gid & 15;
    int ec = min(e, m - 1);
    int a = ea[ec], b = eb[ec];
    const float4* Z4 = (const float4*)Z;
    float4 va = Z4[(size_t)a * 16 + l];
    float4 vb = Z4[(size_t)b * 16 + l];
    float s = va.x * vb.x + va.y * vb.y + va.z * vb.z + va.w * vb.w;
    s += __shfl_xor_sync(0xffffffffu, s, 8);
    s += __shfl_xor_sync(0xffffffffu, s, 4);
    s += __shfl_xor_sync(0xffffffffu, s, 2);
    s += __shfl_xor_sync(0xffffffffu, s, 1);
    if (l == 0 && e < m) P[e] = 1.0f / (1.0f + expf(-s));
}

// ---------------------------------------------------------------- launch
extern "C" void kernel_launch(void* const* d_in, const int* in_sizes, int n_in,
                              void* d_out, int out_size) {
    const float* xs = (const float*)d_in[0];
    const float* xt = (const float*)d_in[1];
    const int*   se = (const int*)d_in[2];
    const int*   te = (const int*)d_in[3];
    const float* W1 = (const float*)d_in[4];
    const float* b1 = (const float*)d_in[5];
    const float* W2 = (const float*)d_in[6];
    const float* b2 = (const float*)d_in[7];
    const float* W3 = (const float*)d_in[8];
    const float* b3 = (const float*)d_in[9];

    int n = in_sizes[0] / 128;   // 100000
    int m = in_sizes[2] / 2;     // 500000

    float* out = (float*)d_out;
    float* zs = out;
    float* zt = out + (size_t)n * 64;
    float* ps = zt + (size_t)n * 64;
    float* pt = ps + m;

    float *hbuf, *hsbuf;
    cudaGetSymbolAddress((void**)&hbuf, g_h);
    cudaGetSymbolAddress((void**)&hsbuf, g_hs);

    int nb      = (n + 1023) / 1024;       // 98
    int gb_n256 = (n + 255) / 256;
    int gb_m512 = (m + 511) / 512;
    int gb_gemm = (n + 63) / 64;
    int gb_agg  = (n + 7) / 8;
    int gb_dec  = (m + 15) / 16;

    // ---- source network ----
    // gemm128 at launch slot 3 (observed ncu capture slot).
    {
        const int* src = se;
        const int* dst = se + m;
        zero_cnt_kernel<<<gb_n256, 256>>>(n);                       // 0
        count_kernel<<<gb_m512, 512>>>(dst, m);                     // 1
        scanA_kernel<<<nb, 1024>>>(n);                              // 2 (dis ready)
        gemm_kernel<128, false><<<gb_gemm, 128>>>(xs, W1, hbuf, n); // 3 <- profiled
        scanB_kernel<<<1, NB_MAX>>>(nb, n);                         // 4
        scanC_kernel<<<nb, 1024>>>(n);                              // 5
        fill_kernel<<<gb_m512, 512>>>(src, dst, m);                 // 6
        agg128_kernel<<<gb_agg, 256>>>(hbuf, b1, hsbuf, n);         // 7
        gemm_kernel<64, true><<<gb_gemm, 128>>>(hsbuf, W3, hbuf, n);
        agg64_kernel<<<gb_agg, 256>>>(hbuf, b3, zs, n);
    }
    // ---- target network ----
    {
        const int* src = te;
        const int* dst = te + m;
        zero_cnt_kernel<<<gb_n256, 256>>>(n);
        count_kernel<<<gb_m512, 512>>>(dst, m);
        scanA_kernel<<<nb, 1024>>>(n);
        scanB_kernel<<<1, NB_MAX>>>(nb, n);
        scanC_kernel<<<nb, 1024>>>(n);
        fill_kernel<<<gb_m512, 512>>>(src, dst, m);
        gemm_kernel<128, false><<<gb_gemm, 128>>>(xt, W2, hbuf, n);
        agg128_kernel<<<gb_agg, 256>>>(hbuf, b2, hsbuf, n);
        gemm_kernel<64, true><<<gb_gemm, 128>>>(hsbuf, W3, hbuf, n);
        agg64_kernel<<<gb_agg, 256>>>(hbuf, b3, zt, n);
    }
    // ---- decoders ----
    decoder_kernel<<<gb_dec, 256>>>(zs, se, se + m, ps, m);
    decoder_kernel<<<gb_dec, 256>>>(zt, te, te + m, pt, m);
}

// round 6
// speedup vs baseline: 2.5131x; 1.0229x over previous
#include <cuda_runtime.h>
#include <math.h>

#define NN 100000
#define EE 500000
#define NB_MAX 128   // ceil(NN/1024) = 98 <= 128

typedef unsigned long long u64;

__device__ __forceinline__ u64 pack2(float lo, float hi) {
    u64 r;
    asm("mov.b64 %0, {%1, %2};" : "=l"(r) : "f"(lo), "f"(hi));
    return r;
}
__device__ __forceinline__ void fma2(u64& d, u64 a, u64 b) {
    asm("fma.rn.f32x2 %0, %1, %2, %0;" : "+l"(d) : "l"(a), "l"(b));
}
__device__ __forceinline__ float2 unpack2(u64 v) {
    float2 f;
    asm("mov.b64 {%0, %1}, %2;" : "=f"(f.x), "=f"(f.y) : "l"(v));
    return f;
}

// Scratch (per-network)
__device__ float g_h [2][NN * 128];
__device__ float g_hs[2][NN * 128];
__device__ int   g_cnt[2][NN];
__device__ int   g_off[2][NN + 1];
__device__ int   g_cur[2][NN];
__device__ int   g_adj[2][EE];
__device__ float g_dis[2][NN];   // rsqrt(deg)
__device__ int   g_bsum[2][NB_MAX];
__device__ int   g_bpre[2][NB_MAX];

// ---------------------------------------------------------------- CSR build
__global__ void zero_cnt_kernel(int n) {
    int i = blockIdx.x * blockDim.x + threadIdx.x;
    if (i < n) g_cnt[blockIdx.y][i] = 0;
}

__global__ void count_kernel(const int* __restrict__ se,
                             const int* __restrict__ te, int m) {
    int net = blockIdx.y;
    const int* dst = (net ? te : se) + m;
    for (int e = blockIdx.x * blockDim.x + threadIdx.x; e < m;
         e += gridDim.x * blockDim.x)
        atomicAdd(&g_cnt[net][dst[e]], 1);
}

__global__ void scanA_kernel(int n) {
    __shared__ int ss[1024];
    int net = blockIdx.y;
    int t = threadIdx.x;
    int i = blockIdx.x * 1024 + t;
    int c = (i < n) ? g_cnt[net][i] : 0;
    ss[t] = c;
    __syncthreads();
    for (int d = 1; d < 1024; d <<= 1) {
        int v = (t >= d) ? ss[t - d] : 0;
        __syncthreads();
        ss[t] += v;
        __syncthreads();
    }
    if (i < n) {
        g_off[net][i] = ss[t] - c;
        g_dis[net][i] = rsqrtf((float)(c + 1));
    }
    if (t == 1023) g_bsum[net][blockIdx.x] = ss[1023];
}

__global__ void scanB_kernel(int nb, int n) {
    __shared__ int ss[NB_MAX];
    int net = blockIdx.y;
    int t = threadIdx.x;
    int c = (t < nb) ? g_bsum[net][t] : 0;
    ss[t] = c;
    __syncthreads();
    for (int d = 1; d < NB_MAX; d <<= 1) {
        int v = (t >= d) ? ss[t - d] : 0;
        __syncthreads();
        ss[t] += v;
        __syncthreads();
    }
    if (t < nb) g_bpre[net][t] = ss[t] - c;
    if (t == NB_MAX - 1) g_off[net][n] = ss[NB_MAX - 1];
}

__global__ void scanC_kernel(int n) {
    int net = blockIdx.y;
    int i = blockIdx.x * 1024 + threadIdx.x;
    if (i < n) {
        int v = g_off[net][i] + g_bpre[net][i >> 10];
        g_off[net][i] = v;
        g_cur[net][i] = v;
    }
}

__global__ void fill_kernel(const int* __restrict__ se,
                            const int* __restrict__ te, int m) {
    int net = blockIdx.y;
    const int* src = net ? te : se;
    const int* dst = src + m;
    for (int e = blockIdx.x * blockDim.x + threadIdx.x; e < m;
         e += gridDim.x * blockDim.x) {
        int p = atomicAdd(&g_cur[net][dst[e]], 1);
        g_adj[net][p] = src[e];
    }
}

// ---------------------------------------------------------------- dense GEMM
// g_h[net][r,:] = (RELU_IN ? relu(X[r]) : X[r]) @ W * dis[r]
// 64-row tile, 128 threads, f32x2 packed FMAs.
// X staged via smem (broadcast across tx); W read directly via __ldg (L1-hot,
// one 128B line per warp per LDG.64) -> no staging, single __syncthreads.
template <int OUTC, bool RELU_IN>
__global__ void __launch_bounds__(128, 4)
gemm_kernel(const float* __restrict__ X0, const float* __restrict__ X1,
            const float* __restrict__ Wa, const float* __restrict__ Wb,
            int n) {
    constexpr int CP2 = OUTC / 32;   // packed col-pairs per thread: 4 or 2
    __shared__ float sx[64 * 128];

    int net = blockIdx.y;
    const float* X = net ? X1 : X0;
    const float* W = net ? Wb : Wa;
    float* H = g_h[net];
    const float* dis = g_dis[net];

    int tid = threadIdx.x;
    int row0 = blockIdx.x * 64;
    const float4* X4 = (const float4*)X;
#pragma unroll
    for (int i = tid; i < 64 * 32; i += 128) {
        int r = i >> 5, c4 = i & 31;
        float4 v = make_float4(0.f, 0.f, 0.f, 0.f);
        if (row0 + r < n) v = X4[(size_t)(row0 + r) * 32 + c4];
        if (RELU_IN) {
            v.x = fmaxf(v.x, 0.f); v.y = fmaxf(v.y, 0.f);
            v.z = fmaxf(v.z, 0.f); v.w = fmaxf(v.w, 0.f);
        }
        ((float4*)sx)[i] = v;
    }
    __syncthreads();

    int tx = tid & 15;     // col pair tx*2 + 32*c
    int ty = tid >> 4;     // 8 row groups (x8 rows)
    u64 acc2[8][CP2];
    u64 zz = pack2(0.f, 0.f);
#pragma unroll
    for (int r = 0; r < 8; r++)
#pragma unroll
        for (int c = 0; c < CP2; c++) acc2[r][c] = zz;

    const u64* wbase = (const u64*)(W + tx * 2);   // +k*OUTC/2 per k, +16c per pair

#pragma unroll 2
    for (int k4 = 0; k4 < 32; k4++) {
        float4 xq[8];
#pragma unroll
        for (int r = 0; r < 8; r++)
            xq[r] = *(const float4*)&sx[(ty * 8 + r) * 128 + k4 * 4];
#pragma unroll
        for (int kk = 0; kk < 4; kk++) {
            int k = k4 * 4 + kk;
            u64 wv2[CP2];
#pragma unroll
            for (int c = 0; c < CP2; c++)
                wv2[c] = __ldg(wbase + (size_t)k * (OUTC / 2) + 16 * c);
#pragma unroll
            for (int r = 0; r < 8; r++) {
                float xv = ((const float*)&xq[r])[kk];
                u64 xp = pack2(xv, xv);
#pragma unroll
                for (int c = 0; c < CP2; c++)
                    fma2(acc2[r][c], xp, wv2[c]);
            }
        }
    }

#pragma unroll
    for (int r = 0; r < 8; r++) {
        int gr = row0 + ty * 8 + r;
        if (gr < n) {
            float ds = dis[gr];
            float* hrow = H + (size_t)gr * OUTC + tx * 2;
#pragma unroll
            for (int c = 0; c < CP2; c++) {
                float2 a = unpack2(acc2[r][c]);
                a.x *= ds; a.y *= ds;
                *(float2*)(hrow + 32 * c) = a;
            }
        }
    }
}

// ---------------------------------------------------------------- aggregation
// out[w] = dis[w] * (h'[w] + sum_j h'[adj[j]]) + bias     (h' pre-scaled by dis)
__global__ void agg128_kernel(const float* __restrict__ b1,
                              const float* __restrict__ b2, int n) {
    int net = blockIdx.y;
    int w = (blockIdx.x * blockDim.x + threadIdx.x) >> 5;
    int lane = threadIdx.x & 31;
    if (w >= n) return;
    const float4* H4 = (const float4*)g_h[net];
    const float* bias = net ? b2 : b1;
    float4 acc = H4[(size_t)w * 32 + lane];
    int b0 = g_off[net][w], e0 = g_off[net][w + 1];
    const int* adj = g_adj[net];
    for (int j = b0; j < e0; j++) {
        int s = adj[j];
        float4 v = H4[(size_t)s * 32 + lane];
        acc.x += v.x; acc.y += v.y; acc.z += v.z; acc.w += v.w;
    }
    float ds = g_dis[net][w];
    float4 bb = ((const float4*)bias)[lane];
    acc.x = acc.x * ds + bb.x;
    acc.y = acc.y * ds + bb.y;
    acc.z = acc.z * ds + bb.z;
    acc.w = acc.w * ds + bb.w;
    ((float4*)g_hs[net])[(size_t)w * 32 + lane] = acc;
}

__global__ void agg64_kernel(const float* __restrict__ bias,
                             float* __restrict__ zs,
                             float* __restrict__ zt, int n) {
    int net = blockIdx.y;
    int w = (blockIdx.x * blockDim.x + threadIdx.x) >> 5;
    int lane = threadIdx.x & 31;
    if (w >= n) return;
    const float2* H2 = (const float2*)g_h[net];
    float2 acc = H2[(size_t)w * 32 + lane];
    int b0 = g_off[net][w], e0 = g_off[net][w + 1];
    const int* adj = g_adj[net];
    for (int j = b0; j < e0; j++) {
        int s = adj[j];
        float2 v = H2[(size_t)s * 32 + lane];
        acc.x += v.x;
        acc.y += v.y;
    }
    float ds = g_dis[net][w];
    float2 bb = ((const float2*)bias)[lane];
    acc.x = acc.x * ds + bb.x;
    acc.y = acc.y * ds + bb.y;
    float* Out = net ? zt : zs;
    ((float2*)Out)[(size_t)w * 32 + lane] = acc;
}

// ---------------------------------------------------------------- decoder
// Both networks in one launch; ps/pt are contiguous in d_out.
__global__ void decoder_kernel(const float* __restrict__ zs,
                               const float* __restrict__ zt,
                               const int* __restrict__ se,
                               const int* __restrict__ te,
                               float* __restrict__ P, int m) {
    int gid = blockIdx.x * blockDim.x + threadIdx.x;
    int e = gid >> 4;          // global edge id in [0, 2m)
    int l = gid & 15;
    int ec = min(e, 2 * m - 1);
    int net = (ec >= m);
    int el = net ? (ec - m) : ec;
    const int* ea = net ? te : se;
    const float* Z = net ? zt : zs;
    int a = ea[el], b = ea[el + m];
    const float4* Z4 = (const float4*)Z;
    float4 va = Z4[(size_t)a * 16 + l];
    float4 vb = Z4[(size_t)b * 16 + l];
    float s = va.x * vb.x + va.y * vb.y + va.z * vb.z + va.w * vb.w;
    s += __shfl_xor_sync(0xffffffffu, s, 8);
    s += __shfl_xor_sync(0xffffffffu, s, 4);
    s += __shfl_xor_sync(0xffffffffu, s, 2);
    s += __shfl_xor_sync(0xffffffffu, s, 1);
    if (l == 0 && e < 2 * m) P[e] = 1.0f / (1.0f + expf(-s));
}

// ---------------------------------------------------------------- launch
extern "C" void kernel_launch(void* const* d_in, const int* in_sizes, int n_in,
                              void* d_out, int out_size) {
    const float* xs = (const float*)d_in[0];
    const float* xt = (const float*)d_in[1];
    const int*   se = (const int*)d_in[2];
    const int*   te = (const int*)d_in[3];
    const float* W1 = (const float*)d_in[4];
    const float* b1 = (const float*)d_in[5];
    const float* W2 = (const float*)d_in[6];
    const float* b2 = (const float*)d_in[7];
    const float* W3 = (const float*)d_in[8];
    const float* b3 = (const float*)d_in[9];

    int n = in_sizes[0] / 128;   // 100000
    int m = in_sizes[2] / 2;     // 500000

    float* out = (float*)d_out;
    float* zs = out;
    float* zt = out + (size_t)n * 64;
    float* ps = zt + (size_t)n * 64;

    float *hsbuf;
    cudaGetSymbolAddress((void**)&hsbuf, g_hs);

    int nb = (n + 1023) / 1024;  // 98
    dim3 gn256((n + 255) / 256, 2);
    dim3 gm512((m + 511) / 512, 2);
    dim3 gscan(nb, 2);
    dim3 gone(1, 2);
    dim3 ggemm((n + 63) / 64, 2);
    dim3 gagg((n + 7) / 8, 2);
    int gb_dec = (2 * m + 15) / 16;

    zero_cnt_kernel<<<gn256, 256>>>(n);                              // 0
    count_kernel<<<gm512, 512>>>(se, te, m);                         // 1
    scanA_kernel<<<gscan, 1024>>>(n);                                // 2 (dis ready)
    gemm_kernel<128, false><<<ggemm, 128>>>(xs, xt, W1, W2, n);      // 3 <- profiled
    scanB_kernel<<<gone, NB_MAX>>>(nb, n);                           // 4
    scanC_kernel<<<gscan, 1024>>>(n);                                // 5
    fill_kernel<<<gm512, 512>>>(se, te, m);                          // 6
    agg128_kernel<<<gagg, 256>>>(b1, b2, n);                         // 7
    gemm_kernel<64, true><<<ggemm, 128>>>(hsbuf, hsbuf + (size_t)NN * 128,
                                          W3, W3, n);                // 8
    agg64_kernel<<<gagg, 256>>>(b3, zs, zt, n);                      // 9
    decoder_kernel<<<gb_dec, 256>>>(zs, zt, se, te, ps, m);          // 10
}

// round 8
// speedup vs baseline: 2.5172x; 1.0017x over previous
#include <cuda_runtime.h>
#include <cuda_bf16.h>
#include <math.h>
#include <cstdint>

#define NN 100000
#define EE 500000
#define NB_MAX 128   // ceil(NN/1024) = 98 <= 128

typedef unsigned int u32;

// ---------------------------------------------------------------- scratch
__device__ float g_h [2][NN * 128];
__device__ float g_hs[2][NN * 128];
__device__ int   g_cnt[2][NN];
__device__ int   g_off[2][NN + 1];
__device__ int   g_cur[2][NN];
__device__ int   g_adj[2][EE];
__device__ float g_dis[2][NN];   // rsqrt(deg)
__device__ int   g_bsum[2][NB_MAX];
__device__ int   g_bpre[2][NB_MAX];
// bf16 hi/lo weight images, TRANSPOSED to [outc][128] (k contiguous)
__device__ __nv_bfloat16 g_Bimg[3][2][128 * 128];

// ---------------------------------------------------------------- mma helper
__device__ __forceinline__ void mma_bf16(float* c, const u32* a, u32 b0, u32 b1) {
    asm volatile(
        "mma.sync.aligned.m16n8k16.row.col.f32.bf16.bf16.f32 "
        "{%0,%1,%2,%3}, {%4,%5,%6,%7}, {%8,%9}, {%0,%1,%2,%3};"
        : "+f"(c[0]), "+f"(c[1]), "+f"(c[2]), "+f"(c[3])
        : "r"(a[0]), "r"(a[1]), "r"(a[2]), "r"(a[3]), "r"(b0), "r"(b1));
}

// ---------------------------------------------------------------- W image prep
__global__ void prep_b_kernel(const float* __restrict__ W1,
                              const float* __restrict__ W2,
                              const float* __restrict__ W3) {
    int idx = blockIdx.x * 256 + threadIdx.x;   // 3*128*128
    if (idx >= 3 * 128 * 128) return;
    int k = idx & 127;
    int c = (idx >> 7) & 127;
    int mtx = idx >> 14;
    int outc = (mtx == 2) ? 64 : 128;
    if (c >= outc) return;
    const float* W = (mtx == 0) ? W1 : ((mtx == 1) ? W2 : W3);
    float w = W[k * outc + c];
    __nv_bfloat16 hi = __float2bfloat16(w);
    __nv_bfloat16 lo = __float2bfloat16(w - __bfloat162float(hi));
    g_Bimg[mtx][0][c * 128 + k] = hi;
    g_Bimg[mtx][1][c * 128 + k] = lo;
}

// ---------------------------------------------------------------- CSR build
__global__ void zero_cnt_kernel(int n) {
    int i = blockIdx.x * blockDim.x + threadIdx.x;
    if (i < n) g_cnt[blockIdx.y][i] = 0;
}

__global__ void count_kernel(const int* __restrict__ se,
                             const int* __restrict__ te, int m) {
    int net = blockIdx.y;
    const int* dst = (net ? te : se) + m;
    for (int e = blockIdx.x * blockDim.x + threadIdx.x; e < m;
         e += gridDim.x * blockDim.x)
        atomicAdd(&g_cnt[net][dst[e]], 1);
}

__global__ void scanA_kernel(int n) {
    __shared__ int ss[1024];
    int net = blockIdx.y;
    int t = threadIdx.x;
    int i = blockIdx.x * 1024 + t;
    int c = (i < n) ? g_cnt[net][i] : 0;
    ss[t] = c;
    __syncthreads();
    for (int d = 1; d < 1024; d <<= 1) {
        int v = (t >= d) ? ss[t - d] : 0;
        __syncthreads();
        ss[t] += v;
        __syncthreads();
    }
    if (i < n) {
        g_off[net][i] = ss[t] - c;
        g_dis[net][i] = rsqrtf((float)(c + 1));
    }
    if (t == 1023) g_bsum[net][blockIdx.x] = ss[1023];
}

__global__ void scanB_kernel(int nb, int n) {
    __shared__ int ss[NB_MAX];
    int net = blockIdx.y;
    int t = threadIdx.x;
    int c = (t < nb) ? g_bsum[net][t] : 0;
    ss[t] = c;
    __syncthreads();
    for (int d = 1; d < NB_MAX; d <<= 1) {
        int v = (t >= d) ? ss[t - d] : 0;
        __syncthreads();
        ss[t] += v;
        __syncthreads();
    }
    if (t < nb) g_bpre[net][t] = ss[t] - c;
    if (t == NB_MAX - 1) g_off[net][n] = ss[NB_MAX - 1];
}

__global__ void scanC_kernel(int n) {
    int net = blockIdx.y;
    int i = blockIdx.x * 1024 + threadIdx.x;
    if (i < n) {
        int v = g_off[net][i] + g_bpre[net][i >> 10];
        g_off[net][i] = v;
        g_cur[net][i] = v;
    }
}

__global__ void fill_kernel(const int* __restrict__ se,
                            const int* __restrict__ te, int m) {
    int net = blockIdx.y;
    const int* src = net ? te : se;
    const int* dst = src + m;
    for (int e = blockIdx.x * blockDim.x + threadIdx.x; e < m;
         e += gridDim.x * blockDim.x) {
        int p = atomicAdd(&g_cur[net][dst[e]], 1);
        g_adj[net][p] = src[e];
    }
}

// ---------------------------------------------------------------- mma GEMM
// g_h[net][r,:] = (relu?)X[r,:] @ W * dis[r]   via bf16-split mma.sync.
// 128-row tile, 256 threads (8 warps), warp owns 16 rows x OUTC cols.
template <int OUTC, bool RELU_IN>
__global__ void __launch_bounds__(256, 1)
gemm_mma_kernel(const float* __restrict__ X0, const float* __restrict__ X1,
                int midx0, int midx1, int n) {
    constexpr int PA = 136;             // bf16 pitch (conflict-free frags)
    constexpr int NT = OUTC / 8;        // n-tiles per warp (16 or 8)
    constexpr int A_BYTES = 128 * PA * 2;
    constexpr int B_BYTES = OUTC * PA * 2;

    extern __shared__ char smem[];
    __nv_bfloat16* sAhi = (__nv_bfloat16*)smem;
    __nv_bfloat16* sAlo = (__nv_bfloat16*)(smem + A_BYTES);
    __nv_bfloat16* sBhi = (__nv_bfloat16*)(smem + 2 * A_BYTES);
    __nv_bfloat16* sBlo = (__nv_bfloat16*)(smem + 2 * A_BYTES + B_BYTES);

    int tid = threadIdx.x;
    int net = blockIdx.y;
    const float* X = net ? X1 : X0;
    int midx = net ? midx1 : midx0;
    int row0 = blockIdx.x * 128;
    const float* dis = g_dis[net];
    float* H = g_h[net];

    // stage B (hi/lo) with pitch
    {
        const u32* bh = (const u32*)g_Bimg[midx][0];
        const u32* bl = (const u32*)g_Bimg[midx][1];
        for (int i = tid; i < OUTC * 64; i += 256) {
            int r = i >> 6, c2 = i & 63;
            u32 d = r * 68 + c2;   // u32 units into pitched smem
            ((u32*)sBhi)[d] = bh[i];
            ((u32*)sBlo)[d] = bl[i];
        }
    }
    // stage X -> bf16 hi/lo
    {
        int r = tid >> 1;
        int c0 = (tid & 1) * 64;
        int gr = row0 + r;
        const float4* xrow = (const float4*)(X + (size_t)gr * 128 + c0);
        u32* ah = (u32*)&sAhi[r * PA + c0];
        u32* al = (u32*)&sAlo[r * PA + c0];
#pragma unroll
        for (int j = 0; j < 16; j++) {
            float4 v = make_float4(0.f, 0.f, 0.f, 0.f);
            if (gr < n) v = xrow[j];
            if (RELU_IN) {
                v.x = fmaxf(v.x, 0.f); v.y = fmaxf(v.y, 0.f);
                v.z = fmaxf(v.z, 0.f); v.w = fmaxf(v.w, 0.f);
            }
            __nv_bfloat162 h0 = make_bfloat162(__float2bfloat16(v.x),
                                               __float2bfloat16(v.y));
            __nv_bfloat162 h1 = make_bfloat162(__float2bfloat16(v.z),
                                               __float2bfloat16(v.w));
            __nv_bfloat162 l0 = make_bfloat162(
                __float2bfloat16(v.x - __bfloat162float(h0.x)),
                __float2bfloat16(v.y - __bfloat162float(h0.y)));
            __nv_bfloat162 l1 = make_bfloat162(
                __float2bfloat16(v.z - __bfloat162float(h1.x)),
                __float2bfloat16(v.w - __bfloat162float(h1.y)));
            ah[2 * j]     = *(u32*)&h0;
            ah[2 * j + 1] = *(u32*)&h1;
            al[2 * j]     = *(u32*)&l0;
            al[2 * j + 1] = *(u32*)&l1;
        }
    }
    __syncthreads();

    int w = tid >> 5, lane = tid & 31;
    int r0 = w * 16;
    int qrow = lane >> 2;          // 0..7
    int qk = (lane & 3) * 2;       // 0,2,4,6

    float acc[NT][4];
#pragma unroll
    for (int t = 0; t < NT; t++)
#pragma unroll
        for (int i = 0; i < 4; i++) acc[t][i] = 0.f;

#pragma unroll
    for (int kc = 0; kc < 128; kc += 16) {
        u32 ah[4], al[4];
        {
            const __nv_bfloat16* base = sAhi + (r0 + qrow) * PA + kc + qk;
            ah[0] = *(const u32*)base;
            ah[1] = *(const u32*)(base + 8 * PA);
            ah[2] = *(const u32*)(base + 8);
            ah[3] = *(const u32*)(base + 8 * PA + 8);
            const __nv_bfloat16* basl = sAlo + (r0 + qrow) * PA + kc + qk;
            al[0] = *(const u32*)basl;
            al[1] = *(const u32*)(basl + 8 * PA);
            al[2] = *(const u32*)(basl + 8);
            al[3] = *(const u32*)(basl + 8 * PA + 8);
        }
#pragma unroll
        for (int t = 0; t < NT; t++) {
            const __nv_bfloat16* bb = sBhi + (t * 8 + qrow) * PA + kc + qk;
            u32 bh0 = *(const u32*)bb;
            u32 bh1 = *(const u32*)(bb + 8);
            mma_bf16(acc[t], ah, bh0, bh1);
            mma_bf16(acc[t], al, bh0, bh1);
            const __nv_bfloat16* bbl = sBlo + (t * 8 + qrow) * PA + kc + qk;
            u32 bl0 = *(const u32*)bbl;
            u32 bl1 = *(const u32*)(bbl + 8);
            mma_bf16(acc[t], ah, bl0, bl1);
        }
    }

    // epilogue: scale by dis[row], store
    {
        int gr0 = row0 + r0 + qrow;
        int gr1 = gr0 + 8;
        float d0 = (gr0 < n) ? dis[gr0] : 0.f;
        float d1 = (gr1 < n) ? dis[gr1] : 0.f;
#pragma unroll
        for (int t = 0; t < NT; t++) {
            int col = t * 8 + qk;
            if (gr0 < n) {
                float2 v = make_float2(acc[t][0] * d0, acc[t][1] * d0);
                *(float2*)&H[(size_t)gr0 * OUTC + col] = v;
            }
            if (gr1 < n) {
                float2 v = make_float2(acc[t][2] * d1, acc[t][3] * d1);
                *(float2*)&H[(size_t)gr1 * OUTC + col] = v;
            }
        }
    }
}

// ---------------------------------------------------------------- aggregation
// out[w] = dis[w] * (h'[w] + sum_j h'[adj[j]]) + bias   (h' pre-scaled by dis)
__global__ void agg128_kernel(const float* __restrict__ b1,
                              const float* __restrict__ b2, int n) {
    int net = blockIdx.y;
    int w = (blockIdx.x * blockDim.x + threadIdx.x) >> 5;
    int lane = threadIdx.x & 31;
    if (w >= n) return;
    const float4* H4 = (const float4*)g_h[net];
    const float* bias = net ? b2 : b1;
    float4 acc = H4[(size_t)w * 32 + lane];
    int b0 = g_off[net][w], e0 = g_off[net][w + 1];
    const int* adj = g_adj[net];
    for (int j = b0; j < e0; j++) {
        int s = adj[j];
        float4 v = H4[(size_t)s * 32 + lane];
        acc.x += v.x; acc.y += v.y; acc.z += v.z; acc.w += v.w;
    }
    float ds = g_dis[net][w];
    float4 bb = ((const float4*)bias)[lane];
    acc.x = acc.x * ds + bb.x;
    acc.y = acc.y * ds + bb.y;
    acc.z = acc.z * ds + bb.z;
    acc.w = acc.w * ds + bb.w;
    ((float4*)g_hs[net])[(size_t)w * 32 + lane] = acc;
}

__global__ void agg64_kernel(const float* __restrict__ bias,
                             float* __restrict__ zs,
                             float* __restrict__ zt, int n) {
    int net = blockIdx.y;
    int w = (blockIdx.x * blockDim.x + threadIdx.x) >> 5;
    int lane = threadIdx.x & 31;
    if (w >= n) return;
    const float2* H2 = (const float2*)g_h[net];
    float2 acc = H2[(size_t)w * 32 + lane];
    int b0 = g_off[net][w], e0 = g_off[net][w + 1];
    const int* adj = g_adj[net];
    for (int j = b0; j < e0; j++) {
        int s = adj[j];
        float2 v = H2[(size_t)s * 32 + lane];
        acc.x += v.x;
        acc.y += v.y;
    }
    float ds = g_dis[net][w];
    float2 bb = ((const float2*)bias)[lane];
    acc.x = acc.x * ds + bb.x;
    acc.y = acc.y * ds + bb.y;
    float* Out = net ? zt : zs;
    ((float2*)Out)[(size_t)w * 32 + lane] = acc;
}

// ---------------------------------------------------------------- decoder
__global__ void decoder_kernel(const float* __restrict__ zs,
                               const float* __restrict__ zt,
                               const int* __restrict__ se,
                               const int* __restrict__ te,
                               float* __restrict__ P, int m) {
    int gid = blockIdx.x * blockDim.x + threadIdx.x;
    int e = gid >> 4;
    int l = gid & 15;
    int ec = min(e, 2 * m - 1);
    int net = (ec >= m);
    int el = net ? (ec - m) : ec;
    const int* ea = net ? te : se;
    const float* Z = net ? zt : zs;
    int a = ea[el], b = ea[el + m];
    const float4* Z4 = (const float4*)Z;
    float4 va = Z4[(size_t)a * 16 + l];
    float4 vb = Z4[(size_t)b * 16 + l];
    float s = va.x * vb.x + va.y * vb.y + va.z * vb.z + va.w * vb.w;
    s += __shfl_xor_sync(0xffffffffu, s, 8);
    s += __shfl_xor_sync(0xffffffffu, s, 4);
    s += __shfl_xor_sync(0xffffffffu, s, 2);
    s += __shfl_xor_sync(0xffffffffu, s, 1);
    if (l == 0 && e < 2 * m) P[e] = 1.0f / (1.0f + expf(-s));
}

// ---------------------------------------------------------------- launch
extern "C" void kernel_launch(void* const* d_in, const int* in_sizes, int n_in,
                              void* d_out, int out_size) {
    const float* xs = (const float*)d_in[0];
    const float* xt = (const float*)d_in[1];
    const int*   se = (const int*)d_in[2];
    const int*   te = (const int*)d_in[3];
    const float* W1 = (const float*)d_in[4];
    const float* b1 = (const float*)d_in[5];
    const float* W2 = (const float*)d_in[6];
    const float* b2 = (const float*)d_in[7];
    const float* W3 = (const float*)d_in[8];
    const float* b3 = (const float*)d_in[9];

    int n = in_sizes[0] / 128;   // 100000
    int m = in_sizes[2] / 2;     // 500000

    float* out = (float*)d_out;
    float* zs = out;
    float* zt = out + (size_t)n * 64;
    float* ps = zt + (size_t)n * 64;

    float *hsbuf;
    cudaGetSymbolAddress((void**)&hsbuf, g_hs);

    const int A_BYTES = 128 * 136 * 2;
    const int SM128 = 2 * A_BYTES + 2 * (128 * 136 * 2);   // 139264
    const int SM64  = 2 * A_BYTES + 2 * (64 * 136 * 2);    // 104448
    cudaFuncSetAttribute(gemm_mma_kernel<128, false>,
                         cudaFuncAttributeMaxDynamicSharedMemorySize, SM128);
    cudaFuncSetAttribute(gemm_mma_kernel<64, true>,
                         cudaFuncAttributeMaxDynamicSharedMemorySize, SM64);

    int nb = (n + 1023) / 1024;  // 98
    dim3 gn256((n + 255) / 256, 2);
    dim3 gm512((m + 511) / 512, 2);
    dim3 gscan(nb, 2);
    dim3 gone(1, 2);
    dim3 gtc((n + 127) / 128, 2);
    dim3 gagg((n + 7) / 8, 2);
    int gb_dec = (2 * m + 15) / 16;

    prep_b_kernel<<<(3 * 128 * 128 + 255) / 256, 256>>>(W1, W2, W3);     // 0
    zero_cnt_kernel<<<gn256, 256>>>(n);                                  // 1
    count_kernel<<<gm512, 512>>>(se, te, m);                             // 2
    scanA_kernel<<<gscan, 1024>>>(n);                                    // 3 (dis ready)
    gemm_mma_kernel<128, false><<<gtc, 256, SM128>>>(xs, xt, 0, 1, n);   // 4
    scanB_kernel<<<gone, NB_MAX>>>(nb, n);                               // 5
    scanC_kernel<<<gscan, 1024>>>(n);                                    // 6
    fill_kernel<<<gm512, 512>>>(se, te, m);                              // 7
    agg128_kernel<<<gagg, 256>>>(b1, b2, n);                             // 8
    gemm_mma_kernel<64, true><<<gtc, 256, SM64>>>(hsbuf,
                                                  hsbuf + (size_t)NN * 128,
                                                  2, 2, n);              // 9
    agg64_kernel<<<gagg, 256>>>(b3, zs, zt, n);                          // 10
    decoder_kernel<<<gb_dec, 256>>>(zs, zt, se, te, ps, m);              // 11
}